// round 16
// baseline (speedup 1.0000x reference)
#include <cuda_runtime.h>
#include <cuda_bf16.h>
#include <math.h>

// Problem constants
#define BB 4
#define CC 512
#define LL 2048
#define HH 8
#define DHD 64
#define BLT (BB * LL)          // 8192
#define N_QKV (3 * CC)         // 1536
#define EPSV 1e-5f
#define SCALEV 0.125f          // 64^-0.5
#define LOG2E 1.4426950408889634f

#define PERM16(x) ((((x) & 3) << 2) | ((x) >> 2))

// Scratch (device globals; allocation-free contract)
__device__ float g_qkv[(size_t)BLT * N_QKV];       // Q region used (natural layout)
__device__ __nv_bfloat16 g_ktb[(size_t)BB * HH * LL * DHD]; // K bf16, dh perm32
__device__ __nv_bfloat16 g_vtb[(size_t)BB * HH * DHD * LL]; // V^T bf16, token perm32
__device__ float g_o[(size_t)BLT * CC];            // attn out, [bl, C] k-permuted cols
__device__ float g_wqkvp[(size_t)N_QKV * CC];      // gamma .* w_qkv, k-permuted
__device__ float g_wprojp[(size_t)CC * CC];        // w_proj, k-permuted
__device__ float g_mu[BLT];                        // LN mean per row
__device__ float g_rs[BLT];                        // LN rstd per row
__device__ float g_cs[N_QKV];                      // colsum of gamma.*w_qkv
__device__ float g_be[N_QKV];                      // b_qkv + beta . w_qkv

// ---------------------------------------------------------------------------
// helpers
// ---------------------------------------------------------------------------
__device__ __forceinline__ void mma_tf32(float c[4], const unsigned a[4],
                                         unsigned b0, unsigned b1) {
    asm volatile(
        "mma.sync.aligned.m16n8k8.row.col.f32.tf32.tf32.f32 "
        "{%0,%1,%2,%3}, {%4,%5,%6,%7}, {%8,%9}, {%0,%1,%2,%3};"
        : "+f"(c[0]), "+f"(c[1]), "+f"(c[2]), "+f"(c[3])
        : "r"(a[0]), "r"(a[1]), "r"(a[2]), "r"(a[3]), "r"(b0), "r"(b1));
}

__device__ __forceinline__ void mma_bf16(float c[4], const unsigned a[4],
                                         unsigned b0, unsigned b1) {
    asm volatile(
        "mma.sync.aligned.m16n8k16.row.col.f32.bf16.bf16.f32 "
        "{%0,%1,%2,%3}, {%4,%5,%6,%7}, {%8,%9}, {%0,%1,%2,%3};"
        : "+f"(c[0]), "+f"(c[1]), "+f"(c[2]), "+f"(c[3])
        : "r"(a[0]), "r"(a[1]), "r"(a[2]), "r"(a[3]), "r"(b0), "r"(b1));
}

__device__ __forceinline__ unsigned packbf(float hi, float lo) {
    unsigned r;
    asm("cvt.rn.bf16x2.f32 %0, %1, %2;" : "=r"(r) : "f"(hi), "f"(lo));
    return r;
}

__device__ __forceinline__ void cpa16(unsigned s, const void* g) {
    asm volatile("cp.async.cg.shared.global [%0], [%1], 16;" :: "r"(s), "l"(g));
}
#define CPA_COMMIT() asm volatile("cp.async.commit_group;")
#define CPA_WAIT(n)  asm volatile("cp.async.wait_group %0;" :: "n"(n))

// ---------------------------------------------------------------------------
// Kernel 1: LN stats only. mu/rstd per (b,l).
// ---------------------------------------------------------------------------
__global__ __launch_bounds__(256) void ln_stats(const float* __restrict__ x)
{
    const int tx = threadIdx.x & 63;
    const int cg = threadIdx.x >> 6;
    const int l = blockIdx.x * 64 + tx;
    const int b = blockIdx.y;
    const size_t base = (size_t)b * CC * LL + l;

    float sum = 0.f, sq = 0.f;
    #pragma unroll 8
    for (int cc = 0; cc < 128; cc++) {
        int c = cg * 128 + cc;
        float v = x[base + (size_t)c * LL];
        sum += v;
        sq += v * v;
    }
    __shared__ float rs[4][64];
    __shared__ float rq[4][64];
    rs[cg][tx] = sum;
    rq[cg][tx] = sq;
    __syncthreads();
    if (cg == 0) {
        float ts = rs[0][tx] + rs[1][tx] + rs[2][tx] + rs[3][tx];
        float tq = rq[0][tx] + rq[1][tx] + rq[2][tx] + rq[3][tx];
        float mean = ts * (1.0f / CC);
        float var = tq * (1.0f / CC) - mean * mean;
        g_mu[b * LL + l] = mean;
        g_rs[b * LL + l] = rsqrtf(var + EPSV);
    }
}

// ---------------------------------------------------------------------------
// Kernel 2: weight prep (unchanged).
// ---------------------------------------------------------------------------
__global__ __launch_bounds__(128) void prep_kernel(
    const float* __restrict__ w_qkv, const float* __restrict__ b_qkv,
    const float* __restrict__ gamma, const float* __restrict__ beta,
    const float* __restrict__ w_proj)
{
    const int n = blockIdx.x;
    const int t = threadIdx.x;
    if (n < N_QKV) {
        const float* wr = w_qkv + (size_t)n * CC;
        float gs = 0.f, bs = 0.f;
        #pragma unroll
        for (int j = 0; j < 4; j++) {
            int k = j * 128 + t;
            float w = wr[k];
            float v = __ldg(&gamma[k]) * w;
            gs += v;
            bs += __ldg(&beta[k]) * w;
            int kp = (k & ~15) | PERM16(k & 15);
            g_wqkvp[(size_t)n * CC + kp] = v;
        }
        __shared__ float sg[128], sb[128];
        sg[t] = gs; sb[t] = bs;
        __syncthreads();
        for (int off = 64; off > 0; off >>= 1) {
            if (t < off) { sg[t] += sg[t + off]; sb[t] += sb[t + off]; }
            __syncthreads();
        }
        if (t == 0) {
            g_cs[n] = sg[0];
            g_be[n] = sb[0] + b_qkv[n];
        }
    } else {
        const int r = n - N_QKV;
        #pragma unroll
        for (int j = 0; j < 4; j++) {
            int k = j * 128 + t;
            int kp = (k & ~15) | PERM16(k & 15);
            g_wprojp[(size_t)r * CC + kp] = w_proj[(size_t)r * CC + k];
        }
    }
}

// ---------------------------------------------------------------------------
// Kernel 3: QKV GEMM (AMAJ x loads), 6-stage pipeline, sync every 2 stages.
// Q region: natural fp32. K region: bf16 g_ktb (dh perm32).
// V region: bf16 transposed g_vtb (token perm32).
// ---------------------------------------------------------------------------
#define QA_W 2176            // 16*136
#define QB_W 2048            // 128*16
#define QSTG (QA_W + QB_W)   // 4224
#define QSMEM (QSTG * 6 * 4) // 101376 B

__global__ __launch_bounds__(256, 2) void qkv_gemm(const float* __restrict__ x)
{
    extern __shared__ unsigned smg[];
    const int m0 = blockIdx.x * 128;
    const int n0 = blockIdx.y * 128;
    const int b = m0 >> 11;
    const int l0 = m0 & (LL - 1);

    const int tid = threadIdx.x;
    const int warp = tid >> 5;
    const int lane = tid & 31;
    const int qr = lane >> 2;
    const int qc = lane & 3;
    const int wm = (warp >> 2) * 64;
    const int wn = (warp & 3) * 32;

    unsigned sbase = (unsigned)__cvta_generic_to_shared(smg);

    auto issue_stage = [&](int kk0, int s) {
        unsigned st = sbase + (unsigned)(s * QSTG) * 4u;
        #pragma unroll
        for (int it = 0; it < 2; it++) {
            int idx = tid + it * 256;        // (k, m4): 16 x 32
            int k = idx >> 5, m4 = idx & 31;
            cpa16(st + (unsigned)(k * 136 + m4 * 4) * 4u,
                  &x[((size_t)(b * CC + kk0 + k)) * LL + l0 + m4 * 4]);
        }
        unsigned bt = st + (unsigned)QA_W * 4u;
        #pragma unroll
        for (int it = 0; it < 2; it++) {
            int idx = tid + it * 256;        // (n, k4): 128 x 4
            int n = idx >> 2, k4 = idx & 3;
            cpa16(bt + (unsigned)(n * 16 + k4 * 4) * 4u,
                  &g_wqkvp[(size_t)(n0 + n) * CC + kk0 + k4 * 4]);
        }
    };

    float acc[4][4][4];
    #pragma unroll
    for (int i = 0; i < 4; i++)
        #pragma unroll
        for (int j = 0; j < 4; j++)
            #pragma unroll
            for (int r = 0; r < 4; r++) acc[i][j][r] = 0.f;

    auto do_stage = [&](int s) {
        const unsigned* As_ = smg + s * QSTG;
        const unsigned* Bs_ = As_ + QA_W;
        uint4 bq[4];
        #pragma unroll
        for (int nt = 0; nt < 4; nt++)
            bq[nt] = *(const uint4*)&Bs_[(wn + nt * 8 + qr) * 16 + 4 * qc];
        #pragma unroll
        for (int ks = 0; ks < 2; ks++) {
            int ksq = ks * 8 + qc;
            unsigned af[4][4];
            #pragma unroll
            for (int mt = 0; mt < 4; mt++) {
                int mb = wm + mt * 16;
                af[mt][0] = As_[ksq * 136 + mb + qr];
                af[mt][1] = As_[ksq * 136 + mb + qr + 8];
                af[mt][2] = As_[(ksq + 4) * 136 + mb + qr];
                af[mt][3] = As_[(ksq + 4) * 136 + mb + qr + 8];
            }
            #pragma unroll
            for (int mt = 0; mt < 4; mt++)
                #pragma unroll
                for (int nt = 0; nt < 4; nt++)
                    mma_tf32(acc[mt][nt], af[mt],
                             ks ? bq[nt].z : bq[nt].x,
                             ks ? bq[nt].w : bq[nt].y);
        }
    };

    issue_stage(0, 0);  CPA_COMMIT();
    issue_stage(16, 1); CPA_COMMIT();
    issue_stage(32, 2); CPA_COMMIT();
    issue_stage(48, 3); CPA_COMMIT();

    for (int kt = 0; kt < 32; kt += 2) {
        CPA_WAIT(2);
        __syncthreads();
        if (kt + 4 < 32) issue_stage((kt + 4) * 16, (kt + 4) % 6);
        CPA_COMMIT();
        if (kt + 5 < 32) issue_stage((kt + 5) * 16, (kt + 5) % 6);
        CPA_COMMIT();
        do_stage(kt % 6);
        do_stage((kt + 1) % 6);
    }

    // epilogue: LN affine fold; K -> g_ktb (perm32 dh); V -> g_vtb (perm32 tok)
    const bool kreg = (n0 >= CC && n0 < 2 * CC);
    const bool vreg = (n0 >= 2 * CC);
    #pragma unroll
    for (int mt = 0; mt < 4; mt++) {
        int ml0 = wm + mt * 16 + qr;
        int ml1 = ml0 + 8;
        float s0 = g_rs[m0 + ml0], u0 = g_mu[m0 + ml0];
        float s1 = g_rs[m0 + ml1], u1 = g_mu[m0 + ml1];
        // V token perm32 offsets: pos = 8a + 4g + 2hi + odd with
        // a=(qr>>1), g=(mt&1), odd=(qr&1); hi=0 for row qr, hi=1 for qr+8
        int tpo0 = 8 * (qr >> 1) + 4 * (mt & 1) + (qr & 1);
        int tpo1 = tpo0 + 2;
        #pragma unroll
        for (int nt = 0; nt < 4; nt++) {
            int n = n0 + wn + nt * 8 + 2 * qc;
            float cs0 = __ldg(&g_cs[n]),     be0 = __ldg(&g_be[n]);
            float cs1 = __ldg(&g_cs[n + 1]), be1 = __ldg(&g_be[n + 1]);
            float v00 = s0 * (acc[mt][nt][0] - u0 * cs0) + be0;
            float v01 = s0 * (acc[mt][nt][1] - u0 * cs1) + be1;
            float v10 = s1 * (acc[mt][nt][2] - u1 * cs0) + be0;
            float v11 = s1 * (acc[mt][nt][3] - u1 * cs1) + be1;
            if (vreg) {
                int hh = (n - 2 * CC) >> 6;
                int dh = (n - 2 * CC) & 63;
                int tq = l0 + wm + (mt >> 1) * 32;     // 32-aligned token base
                size_t vb = ((size_t)(b * HH + hh) * DHD + dh) * LL;
                g_vtb[vb + tq + tpo0]      = __float2bfloat16(v00);
                g_vtb[vb + LL + tq + tpo0] = __float2bfloat16(v01);
                g_vtb[vb + tq + tpo1]      = __float2bfloat16(v10);
                g_vtb[vb + LL + tq + tpo1] = __float2bfloat16(v11);
            } else if (kreg) {
                int dh = (n - CC) & 63;                // even
                int hh = (n - CC) >> 6;
                int a = (dh & 15) >> 1;                // pair idx in 16-group
                int hi = (dh >> 3) & 1;                // upper 8 of 16-group
                int g = (dh >> 4) & 1;                 // 16-group in 32-block
                int np = (dh & ~31) | (((a & 3)) << 3) | (g << 2) | (hi << 1);
                int tok0 = l0 + ml0;
                int tok1 = l0 + ml1;
                size_t kbase = ((size_t)(b * HH + hh) * LL);
                *(unsigned*)&g_ktb[(kbase + tok0) * DHD + np] = packbf(v01, v00);
                *(unsigned*)&g_ktb[(kbase + tok1) * DHD + np] = packbf(v11, v10);
            } else {
                *(float2*)&g_qkv[(size_t)(m0 + ml0) * N_QKV + n] = make_float2(v00, v01);
                *(float2*)&g_qkv[(size_t)(m0 + ml1) * N_QKV + n] = make_float2(v10, v11);
            }
        }
    }
}

// ---------------------------------------------------------------------------
// Kernel 5: proj GEMM + bias + residual, 6-stage pipeline.
// ---------------------------------------------------------------------------
#define PA_W 2048
#define PB_W 2048
#define PSTG (PA_W + PB_W)   // 4096
#define PSMEM (PSTG * 6 * 4) // 98304 B

__global__ __launch_bounds__(256, 2) void proj_gemm(
    const float* __restrict__ bias,
    const float* __restrict__ xres,
    float* __restrict__ Cout)
{
    extern __shared__ unsigned smg[];
    const int m0 = blockIdx.x * 128;
    const int n0 = blockIdx.y * 128;
    const int b = m0 >> 11;
    const int l0 = m0 & (LL - 1);

    const int tid = threadIdx.x;
    const int warp = tid >> 5;
    const int lane = tid & 31;
    const int qr = lane >> 2;
    const int qc = lane & 3;
    const int wm = (warp >> 2) * 64;
    const int wn = (warp & 3) * 32;

    unsigned sbase = (unsigned)__cvta_generic_to_shared(smg);

    auto issue_stage = [&](int kk0, int s) {
        unsigned st = sbase + (unsigned)(s * PSTG) * 4u;
        #pragma unroll
        for (int it = 0; it < 2; it++) {
            int idx = tid + it * 256;
            int m = idx >> 2, k4 = idx & 3;
            cpa16(st + (unsigned)(m * 16 + k4 * 4) * 4u,
                  &g_o[(size_t)(m0 + m) * CC + kk0 + k4 * 4]);
        }
        unsigned bt = st + (unsigned)PA_W * 4u;
        #pragma unroll
        for (int it = 0; it < 2; it++) {
            int idx = tid + it * 256;
            int n = idx >> 2, k4 = idx & 3;
            cpa16(bt + (unsigned)(n * 16 + k4 * 4) * 4u,
                  &g_wprojp[(size_t)(n0 + n) * CC + kk0 + k4 * 4]);
        }
    };

    float acc[4][4][4];
    #pragma unroll
    for (int i = 0; i < 4; i++)
        #pragma unroll
        for (int j = 0; j < 4; j++)
            #pragma unroll
            for (int r = 0; r < 4; r++) acc[i][j][r] = 0.f;

    auto do_stage = [&](int s) {
        const unsigned* As_ = smg + s * PSTG;
        const unsigned* Bs_ = As_ + PA_W;
        uint4 bq[4];
        #pragma unroll
        for (int nt = 0; nt < 4; nt++)
            bq[nt] = *(const uint4*)&Bs_[(wn + nt * 8 + qr) * 16 + 4 * qc];
        #pragma unroll
        for (int mt = 0; mt < 4; mt++) {
            int mb = wm + mt * 16;
            uint4 a0 = *(const uint4*)&As_[(mb + qr) * 16 + 4 * qc];
            uint4 a1 = *(const uint4*)&As_[(mb + qr + 8) * 16 + 4 * qc];
            unsigned af0[4] = {a0.x, a1.x, a0.y, a1.y};
            unsigned af1[4] = {a0.z, a1.z, a0.w, a1.w};
            #pragma unroll
            for (int nt = 0; nt < 4; nt++) {
                mma_tf32(acc[mt][nt], af0, bq[nt].x, bq[nt].y);
                mma_tf32(acc[mt][nt], af1, bq[nt].z, bq[nt].w);
            }
        }
    };

    issue_stage(0, 0);  CPA_COMMIT();
    issue_stage(16, 1); CPA_COMMIT();
    issue_stage(32, 2); CPA_COMMIT();
    issue_stage(48, 3); CPA_COMMIT();

    for (int kt = 0; kt < 32; kt += 2) {
        CPA_WAIT(2);
        __syncthreads();
        if (kt + 4 < 32) issue_stage((kt + 4) * 16, (kt + 4) % 6);
        CPA_COMMIT();
        if (kt + 5 < 32) issue_stage((kt + 5) * 16, (kt + 5) % 6);
        CPA_COMMIT();
        do_stage(kt % 6);
        do_stage((kt + 1) % 6);
    }

    #pragma unroll
    for (int mt = 0; mt < 4; mt++) {
        #pragma unroll
        for (int nt = 0; nt < 4; nt++) {
            int n = n0 + wn + nt * 8 + 2 * qc;
            float b0v = __ldg(&bias[n]);
            float b1v = __ldg(&bias[n + 1]);
            int ml0 = wm + mt * 16 + qr;
            size_t a00 = ((size_t)(b * CC + n)) * LL + l0 + ml0;
            size_t a01 = ((size_t)(b * CC + n + 1)) * LL + l0 + ml0;
            Cout[a00]     = acc[mt][nt][0] + b0v + xres[a00];
            Cout[a01]     = acc[mt][nt][1] + b1v + xres[a01];
            Cout[a00 + 8] = acc[mt][nt][2] + b0v + xres[a00 + 8];
            Cout[a01 + 8] = acc[mt][nt][3] + b1v + xres[a01 + 8];
        }
    }
}

// ---------------------------------------------------------------------------
// Kernel 4: flash attention, all-bf16 MMA. 8 warps / 128 q-rows per CTA,
// 2 CTAs/SM. K+V double-buffered (64-token tiles), 1 sync/tile. Each K/V
// tile now serves 128 q-rows (half the L2 + cp.async traffic of R15).
// Row stride 96 bf16 units; perm32 -> one LDS.128 feeds two MMAs.
// smem (words): K0 3072 @0, K1 @3072, V0 @6144, V1 @9216 = 49152 B.
// ---------------------------------------------------------------------------
#define KVST 96              // bf16 units per row (48 words, conflict-free)
#define AT_K0W 0
#define AT_K1W 3072
#define AT_V0W 6144
#define AT_V1W 9216
#define AT_SMEM_BYTES (12288 * 4)
#define NT (LL / 64)

__global__ __launch_bounds__(256, 2) void attn_mma()
{
    extern __shared__ unsigned sma[];

    const int q0 = blockIdx.x * 128;
    const int h = blockIdx.y;
    const int b = blockIdx.z;

    const int tid = threadIdx.x;
    const int warp = tid >> 5;
    const int lane = tid & 31;
    const int qr = lane >> 2;
    const int qc = lane & 3;
    const int wrow = warp * 16;

    unsigned sbase = (unsigned)__cvta_generic_to_shared(sma);

    const __nv_bfloat16* kb = g_ktb + (size_t)(b * HH + h) * LL * DHD;
    const __nv_bfloat16* vt = g_vtb + (size_t)(b * HH + h) * DHD * LL;

    auto load_K = [&](int kt) {
        unsigned kd = sbase + (unsigned)((kt & 1) ? AT_K1W : AT_K0W) * 4u;
        #pragma unroll
        for (int it = 0; it < 2; it++) {
            int idx = tid + it * 256;      // (j, c8): 64 x 8 chunks of 16B
            int j = idx >> 3, c8 = idx & 7;
            cpa16(kd + (unsigned)(j * KVST * 2 + c8 * 16),
                  kb + (size_t)(kt * 64 + j) * DHD + c8 * 8);
        }
    };
    auto load_V = [&](int kt) {
        unsigned vd = sbase + (unsigned)((kt & 1) ? AT_V1W : AT_V0W) * 4u;
        #pragma unroll
        for (int it = 0; it < 2; it++) {
            int idx = tid + it * 256;      // (dh, c8): 64 x 8 chunks of 16B
            int dh = idx >> 3, c8 = idx & 7;
            cpa16(vd + (unsigned)(dh * KVST * 2 + c8 * 16),
                  vt + (size_t)dh * LL + kt * 64 + c8 * 8);
        }
    };

    load_K(0);
    load_V(0);
    CPA_COMMIT();

    // Q fragments: bf16x2 packed, scaled by SCALE*log2e (Q region natural fp32)
    const float* qptr = g_qkv + ((size_t)(b * LL + q0 + wrow)) * N_QKV + h * DHD;
    const float qsc = SCALEV * LOG2E;
    unsigned qa[4][4];
    #pragma unroll
    for (int g = 0; g < 4; g++) {
        int k0 = g * 16 + 2 * qc;
        qa[g][0] = packbf(qptr[(size_t)qr * N_QKV + k0 + 1] * qsc,
                          qptr[(size_t)qr * N_QKV + k0] * qsc);
        qa[g][1] = packbf(qptr[(size_t)(qr + 8) * N_QKV + k0 + 1] * qsc,
                          qptr[(size_t)(qr + 8) * N_QKV + k0] * qsc);
        qa[g][2] = packbf(qptr[(size_t)qr * N_QKV + k0 + 9] * qsc,
                          qptr[(size_t)qr * N_QKV + k0 + 8] * qsc);
        qa[g][3] = packbf(qptr[(size_t)(qr + 8) * N_QKV + k0 + 9] * qsc,
                          qptr[(size_t)(qr + 8) * N_QKV + k0 + 8] * qsc);
    }

    float oacc[8][4];
    #pragma unroll
    for (int nt = 0; nt < 8; nt++)
        #pragma unroll
        for (int r = 0; r < 4; r++) oacc[nt][r] = 0.f;
    float lp0 = 0.f, lp1 = 0.f;

    for (int kt = 0; kt < NT; kt++) {
        CPA_WAIT(0);
        __syncthreads();
        if (kt + 1 < NT) { load_K(kt + 1); load_V(kt + 1); }
        CPA_COMMIT();

        const unsigned short* Ks_ =
            (const unsigned short*)(sma + ((kt & 1) ? AT_K1W : AT_K0W));
        const unsigned short* Vt_ =
            (const unsigned short*)(sma + ((kt & 1) ? AT_V1W : AT_V0W));

        // ---- S = (Q*scale*log2e) K^T : one LDS.128 feeds two MMAs ----
        float sacc[8][4];
        #pragma unroll
        for (int nt = 0; nt < 8; nt++) {
            #pragma unroll
            for (int r = 0; r < 4; r++) sacc[nt][r] = 0.f;
            const unsigned short* krow = &Ks_[(nt * 8 + qr) * KVST];
            uint4 kv0 = *(const uint4*)&krow[qc * 8];
            uint4 kv1 = *(const uint4*)&krow[32 + qc * 8];
            mma_bf16(sacc[nt], qa[0], kv0.x, kv0.y);
            mma_bf16(sacc[nt], qa[1], kv0.z, kv0.w);
            mma_bf16(sacc[nt], qa[2], kv1.x, kv1.y);
            mma_bf16(sacc[nt], qa[3], kv1.z, kv1.w);
        }

        // ---- softmax numerator: exp2 directly ----
        #pragma unroll
        for (int nt = 0; nt < 8; nt++) {
            sacc[nt][0] = exp2f(sacc[nt][0]);
            sacc[nt][1] = exp2f(sacc[nt][1]);
            sacc[nt][2] = exp2f(sacc[nt][2]);
            sacc[nt][3] = exp2f(sacc[nt][3]);
            lp0 += sacc[nt][0] + sacc[nt][1];
            lp1 += sacc[nt][2] + sacc[nt][3];
        }

        // ---- O += P V : one LDS.128 feeds two MMAs ----
        // 32-token block b32 holds key groups G=2*b32 (units 8qc..+3) and
        // G=2*b32+1 (units 8qc+4..+7). 16-key group G's A-frag comes from
        // sacc[2G], sacc[2G+1] (keys 16G..16G+15) — R13 packing.
        #pragma unroll
        for (int b32 = 0; b32 < 2; b32++) {
            int G0 = 2 * b32;
            int G1 = 2 * b32 + 1;
            unsigned paG0[4], paG1[4];
            paG0[0] = packbf(sacc[2 * G0][1],     sacc[2 * G0][0]);
            paG0[1] = packbf(sacc[2 * G0][3],     sacc[2 * G0][2]);
            paG0[2] = packbf(sacc[2 * G0 + 1][1], sacc[2 * G0 + 1][0]);
            paG0[3] = packbf(sacc[2 * G0 + 1][3], sacc[2 * G0 + 1][2]);
            paG1[0] = packbf(sacc[2 * G1][1],     sacc[2 * G1][0]);
            paG1[1] = packbf(sacc[2 * G1][3],     sacc[2 * G1][2]);
            paG1[2] = packbf(sacc[2 * G1 + 1][1], sacc[2 * G1 + 1][0]);
            paG1[3] = packbf(sacc[2 * G1 + 1][3], sacc[2 * G1 + 1][2]);
            #pragma unroll
            for (int nt = 0; nt < 8; nt++) {
                const unsigned short* vrow = &Vt_[(nt * 8 + qr) * KVST + b32 * 32];
                uint4 vv = *(const uint4*)&vrow[qc * 8];
                mma_bf16(oacc[nt], paG0, vv.x, vv.y);
                mma_bf16(oacc[nt], paG1, vv.z, vv.w);
            }
        }
    }

    // final sum reduction, normalize, store (k-permuted cols)
    lp0 += __shfl_xor_sync(0xffffffffu, lp0, 1);
    lp0 += __shfl_xor_sync(0xffffffffu, lp0, 2);
    lp1 += __shfl_xor_sync(0xffffffffu, lp1, 1);
    lp1 += __shfl_xor_sync(0xffffffffu, lp1, 2);
    float inv0 = 1.0f / lp0;
    float inv1 = 1.0f / lp1;

    size_t row0 = ((size_t)(b * LL + q0 + wrow + qr)) * CC;
    size_t row1 = row0 + (size_t)8 * CC;
    #pragma unroll
    for (int nt = 0; nt < 8; nt++) {
        int c0 = h * DHD + nt * 8 + 2 * qc;
        int cp0 = (c0 & ~15) | PERM16(c0 & 15);
        int cp1 = cp0 + 4;   // perm(c0+1) = perm(c0)+4 for even c0
        g_o[row0 + cp0] = oacc[nt][0] * inv0;
        g_o[row0 + cp1] = oacc[nt][1] * inv0;
        g_o[row1 + cp0] = oacc[nt][2] * inv1;
        g_o[row1 + cp1] = oacc[nt][3] * inv1;
    }
}

// ---------------------------------------------------------------------------
extern "C" void kernel_launch(void* const* d_in, const int* in_sizes, int n_in,
                              void* d_out, int out_size)
{
    const float* x        = (const float*)d_in[0];
    const float* ln_gamma = (const float*)d_in[1];
    const float* ln_beta  = (const float*)d_in[2];
    const float* w_qkv    = (const float*)d_in[3];
    const float* b_qkv    = (const float*)d_in[4];
    const float* w_proj   = (const float*)d_in[5];
    const float* b_proj   = (const float*)d_in[6];
    float* out = (float*)d_out;

    static int attrs_set = 0;
    if (!attrs_set) {
        cudaFuncSetAttribute(attn_mma, cudaFuncAttributeMaxDynamicSharedMemorySize, AT_SMEM_BYTES);
        cudaFuncSetAttribute(qkv_gemm, cudaFuncAttributeMaxDynamicSharedMemorySize, QSMEM);
        cudaFuncSetAttribute(proj_gemm, cudaFuncAttributeMaxDynamicSharedMemorySize, PSMEM);
        attrs_set = 1;
    }

    // 1. LN stats (mu, rstd per row)
    ln_stats<<<dim3(LL / 64, BB), 256>>>(x);

    // 2. Weight prep (gamma-fold + k-permutation + colsums)
    prep_kernel<<<N_QKV + CC, 128>>>(w_qkv, b_qkv, ln_gamma, ln_beta, w_proj);

    // 3. QKV GEMM (6-stage; LN fused; K -> g_ktb perm32; V -> g_vtb perm32)
    qkv_gemm<<<dim3(BLT / 128, N_QKV / 128), 256, QSMEM>>>(x);

    // 4. Attention (128 q-rows/CTA, 8 warps, 2 CTAs/SM; K/V traffic halved)
    attn_mma<<<dim3(LL / 128, HH, BB), 256, AT_SMEM_BYTES>>>();

    // 5. Proj GEMM + bias + residual (6-stage)
    proj_gemm<<<dim3(BLT / 128, CC / 128), 256, PSMEM>>>(b_proj, x, out);
}

// round 17
// speedup vs baseline: 1.3594x; 1.3594x over previous
#include <cuda_runtime.h>
#include <cuda_bf16.h>
#include <math.h>

// Problem constants
#define BB 4
#define CC 512
#define LL 2048
#define HH 8
#define DHD 64
#define BLT (BB * LL)          // 8192
#define N_QKV (3 * CC)         // 1536
#define EPSV 1e-5f
#define SCALEV 0.125f          // 64^-0.5
#define LOG2E 1.4426950408889634f

// perm32 (even c): pairs (c,c+1) -> positions (np, np+1)
// np = base32 | ((c>>1)&3)<<3 | ((c>>4)&1)<<2 | ((c>>3)&1)<<1
#define NP32(c) (((c) & ~31) | ((((c) >> 1) & 3) << 3) | \
                 ((((c) >> 4) & 1) << 2) | ((((c) >> 3) & 1) << 1))

// Scratch (device globals; allocation-free contract)
__device__ float g_qkv[(size_t)BLT * N_QKV];               // Q region (natural fp32)
__device__ __nv_bfloat16 g_xtb[(size_t)BLT * CC];          // x^T bf16 [m][k perm32]
__device__ __nv_bfloat16 g_ktb[(size_t)BB * HH * LL * DHD]; // K bf16, dh perm32
__device__ __nv_bfloat16 g_vtb[(size_t)BB * HH * DHD * LL]; // V^T bf16, token perm32
__device__ __nv_bfloat16 g_ob[(size_t)BLT * CC];           // attn out bf16 [m][c perm32]
__device__ __nv_bfloat16 g_wqkvb[(size_t)N_QKV * CC];      // gamma.*w_qkv bf16, k perm32
__device__ __nv_bfloat16 g_wprojb[(size_t)CC * CC];        // w_proj bf16, k perm32
__device__ float g_mu[BLT];
__device__ float g_rs[BLT];
__device__ float g_cs[N_QKV];                              // colsum of bf16(gamma.*w)
__device__ float g_be[N_QKV];                              // b_qkv + beta . w_qkv

// ---------------------------------------------------------------------------
// helpers
// ---------------------------------------------------------------------------
__device__ __forceinline__ void mma_bf16(float c[4], const unsigned a[4],
                                         unsigned b0, unsigned b1) {
    asm volatile(
        "mma.sync.aligned.m16n8k16.row.col.f32.bf16.bf16.f32 "
        "{%0,%1,%2,%3}, {%4,%5,%6,%7}, {%8,%9}, {%0,%1,%2,%3};"
        : "+f"(c[0]), "+f"(c[1]), "+f"(c[2]), "+f"(c[3])
        : "r"(a[0]), "r"(a[1]), "r"(a[2]), "r"(a[3]), "r"(b0), "r"(b1));
}

__device__ __forceinline__ unsigned packbf(float hi, float lo) {
    unsigned r;
    asm("cvt.rn.bf16x2.f32 %0, %1, %2;" : "=r"(r) : "f"(hi), "f"(lo));
    return r;
}

__device__ __forceinline__ void cpa16(unsigned s, const void* g) {
    asm volatile("cp.async.cg.shared.global [%0], [%1], 16;" :: "r"(s), "l"(g));
}
#define CPA_COMMIT() asm volatile("cp.async.commit_group;")
#define CPA_WAIT(n)  asm volatile("cp.async.wait_group %0;" :: "n"(n))

// ---------------------------------------------------------------------------
// Kernel 1: LN stats + bf16 transposed-permuted x.
// Block: 256 threads, 64 l-positions; 8 chunks of 64 c.
// ---------------------------------------------------------------------------
__global__ __launch_bounds__(256) void lnx_kernel(const float* __restrict__ x)
{
    __shared__ float tile[64][65];
    __shared__ float rsum[4][64], rsq[4][64];

    const int tid = threadIdx.x;
    const int l0 = blockIdx.x * 64;
    const int b = blockIdx.y;
    const int lw = tid & 63;
    const int cg = tid >> 6;
    const int wrow = tid >> 2;     // write row 0..63
    const int q = tid & 3;         // c-quarter 0..3

    float sum = 0.f, sq = 0.f;

    for (int ch = 0; ch < 8; ch++) {
        #pragma unroll
        for (int r = 0; r < 4; r++) {
            int idx = tid + r * 256;           // (cp, f4): 64 x 16
            int cp = idx >> 4, f4 = idx & 15;
            float4 v = *(const float4*)&x[((size_t)(b * CC + ch * 64 + cp)) * LL + l0 + f4 * 4];
            tile[cp][f4 * 4 + 0] = v.x;
            tile[cp][f4 * 4 + 1] = v.y;
            tile[cp][f4 * 4 + 2] = v.z;
            tile[cp][f4 * 4 + 3] = v.w;
        }
        __syncthreads();

        // stats (per l = lw, over this chunk's quarter cg)
        #pragma unroll
        for (int i = 0; i < 16; i++) {
            float v = tile[cg * 16 + i][lw];
            sum += v;
            sq += v * v;
        }

        // transposed bf16 write, perm32, coalesced (4 threads per row)
        size_t orow = (size_t)(b * LL + l0 + wrow) * CC + ch * 64 + (q >> 1) * 32;
        int g4 = (q & 1) * 4;
        #pragma unroll
        for (int A = 0; A < 4; A++) {
            int j0 = 2 * A;        // pair (j0, j0+1), (j0+8, j0+9)
            float f00 = tile[q * 16 + j0][wrow];
            float f01 = tile[q * 16 + j0 + 1][wrow];
            float f10 = tile[q * 16 + j0 + 8][wrow];
            float f11 = tile[q * 16 + j0 + 9][wrow];
            uint2 val;
            val.x = packbf(f01, f00);
            val.y = packbf(f11, f10);
            *(uint2*)&g_xtb[orow + 8 * A + g4] = val;
        }
        __syncthreads();
    }

    rsum[cg][lw] = sum;
    rsq[cg][lw] = sq;
    __syncthreads();
    if (cg == 0) {
        float ts = rsum[0][lw] + rsum[1][lw] + rsum[2][lw] + rsum[3][lw];
        float tq = rsq[0][lw] + rsq[1][lw] + rsq[2][lw] + rsq[3][lw];
        float mean = ts * (1.0f / CC);
        float var = tq * (1.0f / CC) - mean * mean;
        g_mu[b * LL + l0 + lw] = mean;
        g_rs[b * LL + l0 + lw] = rsqrtf(var + EPSV);
    }
}

// ---------------------------------------------------------------------------
// Kernel 2: weight prep -> bf16, k perm32.
// ---------------------------------------------------------------------------
__global__ __launch_bounds__(128) void prep_kernel(
    const float* __restrict__ w_qkv, const float* __restrict__ b_qkv,
    const float* __restrict__ gamma, const float* __restrict__ beta,
    const float* __restrict__ w_proj)
{
    const int n = blockIdx.x;
    const int t = threadIdx.x;
    if (n < N_QKV) {
        const float* wr = w_qkv + (size_t)n * CC;
        float gs = 0.f, bs = 0.f;
        #pragma unroll
        for (int j = 0; j < 4; j++) {
            int k = j * 128 + t;
            float w = wr[k];
            __nv_bfloat16 vb = __float2bfloat16(__ldg(&gamma[k]) * w);
            gs += __bfloat162float(vb);        // colsum of the bf16 values
            bs += __ldg(&beta[k]) * w;
            int kp = NP32(k & ~1) | (k & 1);
            g_wqkvb[(size_t)n * CC + kp] = vb;
        }
        __shared__ float sg[128], sb[128];
        sg[t] = gs; sb[t] = bs;
        __syncthreads();
        for (int off = 64; off > 0; off >>= 1) {
            if (t < off) { sg[t] += sg[t + off]; sb[t] += sb[t + off]; }
            __syncthreads();
        }
        if (t == 0) {
            g_cs[n] = sg[0];
            g_be[n] = sb[0] + b_qkv[n];
        }
    } else {
        const int r = n - N_QKV;
        #pragma unroll
        for (int j = 0; j < 4; j++) {
            int k = j * 128 + t;
            int kp = NP32(k & ~1) | (k & 1);
            g_wprojb[(size_t)r * CC + kp] = __float2bfloat16(w_proj[(size_t)r * CC + k]);
        }
    }
}

// ---------------------------------------------------------------------------
// bf16 GEMM constants: BM=BN=128, BK=32, 4 stages.
// Stage = A 128x32 bf16 (4096 ush) + B 128x32 (4096 ush) = 16 KB.
// ---------------------------------------------------------------------------
#define GSTG_H 8192               // ushorts per stage
#define GSMEM (GSTG_H * 2 * 4)    // 65536 B (4 stages)

// ---------------------------------------------------------------------------
// Kernel 3: QKV GEMM, all-bf16, fused LN affine epilogue.
// A = g_xtb, B = g_wqkvb. Q -> g_qkv fp32; K -> g_ktb; V -> g_vtb.
// ---------------------------------------------------------------------------
__global__ __launch_bounds__(256, 2) void qkv_gemm()
{
    extern __shared__ unsigned short smh[];
    const int m0 = blockIdx.x * 128;
    const int n0 = blockIdx.y * 128;
    const int b = m0 >> 11;
    const int l0 = m0 & (LL - 1);

    const int tid = threadIdx.x;
    const int warp = tid >> 5;
    const int lane = tid & 31;
    const int qr = lane >> 2;
    const int qc = lane & 3;
    const int wm = (warp >> 2) * 64;
    const int wn = (warp & 3) * 32;

    unsigned sbase = (unsigned)__cvta_generic_to_shared(smh);

    auto issue_stage = [&](int kk0, int s) {
        unsigned st = sbase + (unsigned)(s * GSTG_H) * 2u;
        #pragma unroll
        for (int it = 0; it < 2; it++) {
            int idx = tid + it * 256;      // (m, c8): 128 x 4 chunks of 16B
            int m = idx >> 2, c8 = idx & 3;
            cpa16(st + (unsigned)(m * 32 + c8 * 8) * 2u,
                  &g_xtb[(size_t)(m0 + m) * CC + kk0 + c8 * 8]);
        }
        unsigned bt = st + 4096u * 2u;
        #pragma unroll
        for (int it = 0; it < 2; it++) {
            int idx = tid + it * 256;
            int n = idx >> 2, c8 = idx & 3;
            cpa16(bt + (unsigned)(n * 32 + c8 * 8) * 2u,
                  &g_wqkvb[(size_t)(n0 + n) * CC + kk0 + c8 * 8]);
        }
    };

    float acc[4][4][4];
    #pragma unroll
    for (int i = 0; i < 4; i++)
        #pragma unroll
        for (int j = 0; j < 4; j++)
            #pragma unroll
            for (int r = 0; r < 4; r++) acc[i][j][r] = 0.f;

    auto do_stage = [&](int s) {
        const unsigned short* As_ = smh + s * GSTG_H;
        const unsigned short* Bs_ = As_ + 4096;
        uint4 bq[4];
        #pragma unroll
        for (int nt = 0; nt < 4; nt++)
            bq[nt] = *(const uint4*)&Bs_[(wn + nt * 8 + qr) * 32 + qc * 8];
        #pragma unroll
        for (int mt = 0; mt < 4; mt++) {
            int mb = wm + mt * 16;
            uint4 rA = *(const uint4*)&As_[(mb + qr) * 32 + qc * 8];
            uint4 rB = *(const uint4*)&As_[(mb + qr + 8) * 32 + qc * 8];
            unsigned ag0[4] = {rA.x, rB.x, rA.y, rB.y};
            unsigned ag1[4] = {rA.z, rB.z, rA.w, rB.w};
            #pragma unroll
            for (int nt = 0; nt < 4; nt++) {
                mma_bf16(acc[mt][nt], ag0, bq[nt].x, bq[nt].y);
                mma_bf16(acc[mt][nt], ag1, bq[nt].z, bq[nt].w);
            }
        }
    };

    issue_stage(0, 0);  CPA_COMMIT();
    issue_stage(32, 1); CPA_COMMIT();
    issue_stage(64, 2); CPA_COMMIT();

    for (int kt = 0; kt < 16; kt++) {
        CPA_WAIT(2);
        __syncthreads();
        if (kt + 3 < 16) issue_stage((kt + 3) * 32, (kt + 3) & 3);
        CPA_COMMIT();
        do_stage(kt & 3);
    }

    // epilogue: LN affine fold; Q fp32; K -> g_ktb; V -> g_vtb
    const bool kreg = (n0 >= CC && n0 < 2 * CC);
    const bool vreg = (n0 >= 2 * CC);
    #pragma unroll
    for (int mt = 0; mt < 4; mt++) {
        int ml0 = wm + mt * 16 + qr;
        int ml1 = ml0 + 8;
        float s0 = g_rs[m0 + ml0], u0 = g_mu[m0 + ml0];
        float s1 = g_rs[m0 + ml1], u1 = g_mu[m0 + ml1];
        // V token perm32: pos = 8a+4g+2hi+odd, a=(qr>>1), g=(mt&1), odd=(qr&1)
        int tpo0 = 8 * (qr >> 1) + 4 * (mt & 1) + (qr & 1);
        int tpo1 = tpo0 + 2;
        #pragma unroll
        for (int nt = 0; nt < 4; nt++) {
            int n = n0 + wn + nt * 8 + 2 * qc;
            float cs0 = __ldg(&g_cs[n]),     be0 = __ldg(&g_be[n]);
            float cs1 = __ldg(&g_cs[n + 1]), be1 = __ldg(&g_be[n + 1]);
            float v00 = s0 * (acc[mt][nt][0] - u0 * cs0) + be0;
            float v01 = s0 * (acc[mt][nt][1] - u0 * cs1) + be1;
            float v10 = s1 * (acc[mt][nt][2] - u1 * cs0) + be0;
            float v11 = s1 * (acc[mt][nt][3] - u1 * cs1) + be1;
            if (vreg) {
                int hh = (n - 2 * CC) >> 6;
                int dh = (n - 2 * CC) & 63;
                int tq = l0 + wm + (mt >> 1) * 32;     // 32-aligned token base
                size_t vb = ((size_t)(b * HH + hh) * DHD + dh) * LL;
                g_vtb[vb + tq + tpo0]      = __float2bfloat16(v00);
                g_vtb[vb + LL + tq + tpo0] = __float2bfloat16(v01);
                g_vtb[vb + tq + tpo1]      = __float2bfloat16(v10);
                g_vtb[vb + LL + tq + tpo1] = __float2bfloat16(v11);
            } else if (kreg) {
                int dh = (n - CC) & 63;                // even
                int hh = (n - CC) >> 6;
                int np = NP32(dh);
                int tok0 = l0 + ml0;
                int tok1 = l0 + ml1;
                size_t kbase = ((size_t)(b * HH + hh) * LL);
                *(unsigned*)&g_ktb[(kbase + tok0) * DHD + np] = packbf(v01, v00);
                *(unsigned*)&g_ktb[(kbase + tok1) * DHD + np] = packbf(v11, v10);
            } else {
                *(float2*)&g_qkv[(size_t)(m0 + ml0) * N_QKV + n] = make_float2(v00, v01);
                *(float2*)&g_qkv[(size_t)(m0 + ml1) * N_QKV + n] = make_float2(v10, v11);
            }
        }
    }
}

// ---------------------------------------------------------------------------
// Kernel 5: proj GEMM (all-bf16) + bias + residual, out [B,C,L] fp32.
// A = g_ob (bf16 perm32), B = g_wprojb.
// ---------------------------------------------------------------------------
__global__ __launch_bounds__(256, 2) void proj_gemm(
    const float* __restrict__ bias,
    const float* __restrict__ xres,
    float* __restrict__ Cout)
{
    extern __shared__ unsigned short smh[];
    const int m0 = blockIdx.x * 128;
    const int n0 = blockIdx.y * 128;
    const int b = m0 >> 11;
    const int l0 = m0 & (LL - 1);

    const int tid = threadIdx.x;
    const int warp = tid >> 5;
    const int lane = tid & 31;
    const int qr = lane >> 2;
    const int qc = lane & 3;
    const int wm = (warp >> 2) * 64;
    const int wn = (warp & 3) * 32;

    unsigned sbase = (unsigned)__cvta_generic_to_shared(smh);

    auto issue_stage = [&](int kk0, int s) {
        unsigned st = sbase + (unsigned)(s * GSTG_H) * 2u;
        #pragma unroll
        for (int it = 0; it < 2; it++) {
            int idx = tid + it * 256;
            int m = idx >> 2, c8 = idx & 3;
            cpa16(st + (unsigned)(m * 32 + c8 * 8) * 2u,
                  &g_ob[(size_t)(m0 + m) * CC + kk0 + c8 * 8]);
        }
        unsigned bt = st + 4096u * 2u;
        #pragma unroll
        for (int it = 0; it < 2; it++) {
            int idx = tid + it * 256;
            int n = idx >> 2, c8 = idx & 3;
            cpa16(bt + (unsigned)(n * 32 + c8 * 8) * 2u,
                  &g_wprojb[(size_t)(n0 + n) * CC + kk0 + c8 * 8]);
        }
    };

    float acc[4][4][4];
    #pragma unroll
    for (int i = 0; i < 4; i++)
        #pragma unroll
        for (int j = 0; j < 4; j++)
            #pragma unroll
            for (int r = 0; r < 4; r++) acc[i][j][r] = 0.f;

    auto do_stage = [&](int s) {
        const unsigned short* As_ = smh + s * GSTG_H;
        const unsigned short* Bs_ = As_ + 4096;
        uint4 bq[4];
        #pragma unroll
        for (int nt = 0; nt < 4; nt++)
            bq[nt] = *(const uint4*)&Bs_[(wn + nt * 8 + qr) * 32 + qc * 8];
        #pragma unroll
        for (int mt = 0; mt < 4; mt++) {
            int mb = wm + mt * 16;
            uint4 rA = *(const uint4*)&As_[(mb + qr) * 32 + qc * 8];
            uint4 rB = *(const uint4*)&As_[(mb + qr + 8) * 32 + qc * 8];
            unsigned ag0[4] = {rA.x, rB.x, rA.y, rB.y};
            unsigned ag1[4] = {rA.z, rB.z, rA.w, rB.w};
            #pragma unroll
            for (int nt = 0; nt < 4; nt++) {
                mma_bf16(acc[mt][nt], ag0, bq[nt].x, bq[nt].y);
                mma_bf16(acc[mt][nt], ag1, bq[nt].z, bq[nt].w);
            }
        }
    };

    issue_stage(0, 0);  CPA_COMMIT();
    issue_stage(32, 1); CPA_COMMIT();
    issue_stage(64, 2); CPA_COMMIT();

    for (int kt = 0; kt < 16; kt++) {
        CPA_WAIT(2);
        __syncthreads();
        if (kt + 3 < 16) issue_stage((kt + 3) * 32, (kt + 3) & 3);
        CPA_COMMIT();
        do_stage(kt & 3);
    }

    #pragma unroll
    for (int mt = 0; mt < 4; mt++) {
        #pragma unroll
        for (int nt = 0; nt < 4; nt++) {
            int n = n0 + wn + nt * 8 + 2 * qc;
            float b0v = __ldg(&bias[n]);
            float b1v = __ldg(&bias[n + 1]);
            int ml0 = wm + mt * 16 + qr;
            size_t a00 = ((size_t)(b * CC + n)) * LL + l0 + ml0;
            size_t a01 = ((size_t)(b * CC + n + 1)) * LL + l0 + ml0;
            Cout[a00]     = acc[mt][nt][0] + b0v + xres[a00];
            Cout[a01]     = acc[mt][nt][1] + b1v + xres[a01];
            Cout[a00 + 8] = acc[mt][nt][2] + b0v + xres[a00 + 8];
            Cout[a01 + 8] = acc[mt][nt][3] + b1v + xres[a01 + 8];
        }
    }
}

// ---------------------------------------------------------------------------
// Kernel 4: flash attention (R15 config: 64 q-rows, 4 warps, 4 CTAs/SM).
// Output -> g_ob bf16 with perm32 channel layout.
// ---------------------------------------------------------------------------
#define KVST 96
#define AT_K0W 0
#define AT_K1W 3072
#define AT_V0W 6144
#define AT_V1W 9216
#define AT_SMEM_BYTES (12288 * 4)
#define NT (LL / 64)

__global__ __launch_bounds__(128, 4) void attn_mma()
{
    extern __shared__ unsigned sma[];

    const int q0 = blockIdx.x * 64;
    const int h = blockIdx.y;
    const int b = blockIdx.z;

    const int tid = threadIdx.x;
    const int warp = tid >> 5;
    const int lane = tid & 31;
    const int qr = lane >> 2;
    const int qc = lane & 3;
    const int wrow = warp * 16;

    unsigned sbase = (unsigned)__cvta_generic_to_shared(sma);

    const __nv_bfloat16* kb = g_ktb + (size_t)(b * HH + h) * LL * DHD;
    const __nv_bfloat16* vt = g_vtb + (size_t)(b * HH + h) * DHD * LL;

    auto load_K = [&](int kt) {
        unsigned kd = sbase + (unsigned)((kt & 1) ? AT_K1W : AT_K0W) * 4u;
        #pragma unroll
        for (int it = 0; it < 4; it++) {
            int idx = tid + it * 128;
            int j = idx >> 3, c8 = idx & 7;
            cpa16(kd + (unsigned)(j * KVST * 2 + c8 * 16),
                  kb + (size_t)(kt * 64 + j) * DHD + c8 * 8);
        }
    };
    auto load_V = [&](int kt) {
        unsigned vd = sbase + (unsigned)((kt & 1) ? AT_V1W : AT_V0W) * 4u;
        #pragma unroll
        for (int it = 0; it < 4; it++) {
            int idx = tid + it * 128;
            int dh = idx >> 3, c8 = idx & 7;
            cpa16(vd + (unsigned)(dh * KVST * 2 + c8 * 16),
                  vt + (size_t)dh * LL + kt * 64 + c8 * 8);
        }
    };

    load_K(0);
    load_V(0);
    CPA_COMMIT();

    const float* qptr = g_qkv + ((size_t)(b * LL + q0 + wrow)) * N_QKV + h * DHD;
    const float qsc = SCALEV * LOG2E;
    unsigned qa[4][4];
    #pragma unroll
    for (int g = 0; g < 4; g++) {
        int k0 = g * 16 + 2 * qc;
        qa[g][0] = packbf(qptr[(size_t)qr * N_QKV + k0 + 1] * qsc,
                          qptr[(size_t)qr * N_QKV + k0] * qsc);
        qa[g][1] = packbf(qptr[(size_t)(qr + 8) * N_QKV + k0 + 1] * qsc,
                          qptr[(size_t)(qr + 8) * N_QKV + k0] * qsc);
        qa[g][2] = packbf(qptr[(size_t)qr * N_QKV + k0 + 9] * qsc,
                          qptr[(size_t)qr * N_QKV + k0 + 8] * qsc);
        qa[g][3] = packbf(qptr[(size_t)(qr + 8) * N_QKV + k0 + 9] * qsc,
                          qptr[(size_t)(qr + 8) * N_QKV + k0 + 8] * qsc);
    }

    float oacc[8][4];
    #pragma unroll
    for (int nt = 0; nt < 8; nt++)
        #pragma unroll
        for (int r = 0; r < 4; r++) oacc[nt][r] = 0.f;
    float lp0 = 0.f, lp1 = 0.f;

    for (int kt = 0; kt < NT; kt++) {
        CPA_WAIT(0);
        __syncthreads();
        if (kt + 1 < NT) { load_K(kt + 1); load_V(kt + 1); }
        CPA_COMMIT();

        const unsigned short* Ks_ =
            (const unsigned short*)(sma + ((kt & 1) ? AT_K1W : AT_K0W));
        const unsigned short* Vt_ =
            (const unsigned short*)(sma + ((kt & 1) ? AT_V1W : AT_V0W));

        float sacc[8][4];
        #pragma unroll
        for (int nt = 0; nt < 8; nt++) {
            #pragma unroll
            for (int r = 0; r < 4; r++) sacc[nt][r] = 0.f;
            const unsigned short* krow = &Ks_[(nt * 8 + qr) * KVST];
            uint4 kv0 = *(const uint4*)&krow[qc * 8];
            uint4 kv1 = *(const uint4*)&krow[32 + qc * 8];
            mma_bf16(sacc[nt], qa[0], kv0.x, kv0.y);
            mma_bf16(sacc[nt], qa[1], kv0.z, kv0.w);
            mma_bf16(sacc[nt], qa[2], kv1.x, kv1.y);
            mma_bf16(sacc[nt], qa[3], kv1.z, kv1.w);
        }

        #pragma unroll
        for (int nt = 0; nt < 8; nt++) {
            sacc[nt][0] = exp2f(sacc[nt][0]);
            sacc[nt][1] = exp2f(sacc[nt][1]);
            sacc[nt][2] = exp2f(sacc[nt][2]);
            sacc[nt][3] = exp2f(sacc[nt][3]);
            lp0 += sacc[nt][0] + sacc[nt][1];
            lp1 += sacc[nt][2] + sacc[nt][3];
        }

        #pragma unroll
        for (int b32 = 0; b32 < 2; b32++) {
            int G0 = 2 * b32;
            int G1 = 2 * b32 + 1;
            unsigned paG0[4], paG1[4];
            paG0[0] = packbf(sacc[2 * G0][1],     sacc[2 * G0][0]);
            paG0[1] = packbf(sacc[2 * G0][3],     sacc[2 * G0][2]);
            paG0[2] = packbf(sacc[2 * G0 + 1][1], sacc[2 * G0 + 1][0]);
            paG0[3] = packbf(sacc[2 * G0 + 1][3], sacc[2 * G0 + 1][2]);
            paG1[0] = packbf(sacc[2 * G1][1],     sacc[2 * G1][0]);
            paG1[1] = packbf(sacc[2 * G1][3],     sacc[2 * G1][2]);
            paG1[2] = packbf(sacc[2 * G1 + 1][1], sacc[2 * G1 + 1][0]);
            paG1[3] = packbf(sacc[2 * G1 + 1][3], sacc[2 * G1 + 1][2]);
            #pragma unroll
            for (int nt = 0; nt < 8; nt++) {
                const unsigned short* vrow = &Vt_[(nt * 8 + qr) * KVST + b32 * 32];
                uint4 vv = *(const uint4*)&vrow[qc * 8];
                mma_bf16(oacc[nt], paG0, vv.x, vv.y);
                mma_bf16(oacc[nt], paG1, vv.z, vv.w);
            }
        }
    }

    lp0 += __shfl_xor_sync(0xffffffffu, lp0, 1);
    lp0 += __shfl_xor_sync(0xffffffffu, lp0, 2);
    lp1 += __shfl_xor_sync(0xffffffffu, lp1, 1);
    lp1 += __shfl_xor_sync(0xffffffffu, lp1, 2);
    float inv0 = 1.0f / lp0;
    float inv1 = 1.0f / lp1;

    // store to g_ob bf16, channel perm32
    size_t row0 = ((size_t)(b * LL + q0 + wrow + qr)) * CC;
    size_t row1 = row0 + (size_t)8 * CC;
    #pragma unroll
    for (int nt = 0; nt < 8; nt++) {
        int c0 = h * DHD + nt * 8 + 2 * qc;       // even
        int np = NP32(c0);
        *(unsigned*)&g_ob[row0 + np] = packbf(oacc[nt][1] * inv0, oacc[nt][0] * inv0);
        *(unsigned*)&g_ob[row1 + np] = packbf(oacc[nt][3] * inv1, oacc[nt][2] * inv1);
    }
}

// ---------------------------------------------------------------------------
extern "C" void kernel_launch(void* const* d_in, const int* in_sizes, int n_in,
                              void* d_out, int out_size)
{
    const float* x        = (const float*)d_in[0];
    const float* ln_gamma = (const float*)d_in[1];
    const float* ln_beta  = (const float*)d_in[2];
    const float* w_qkv    = (const float*)d_in[3];
    const float* b_qkv    = (const float*)d_in[4];
    const float* w_proj   = (const float*)d_in[5];
    const float* b_proj   = (const float*)d_in[6];
    float* out = (float*)d_out;

    static int attrs_set = 0;
    if (!attrs_set) {
        cudaFuncSetAttribute(attn_mma, cudaFuncAttributeMaxDynamicSharedMemorySize, AT_SMEM_BYTES);
        cudaFuncSetAttribute(qkv_gemm, cudaFuncAttributeMaxDynamicSharedMemorySize, GSMEM);
        cudaFuncSetAttribute(proj_gemm, cudaFuncAttributeMaxDynamicSharedMemorySize, GSMEM);
        attrs_set = 1;
    }

    // 1. LN stats + bf16 transposed x (k perm32)
    lnx_kernel<<<dim3(LL / 64, BB), 256>>>(x);

    // 2. Weight prep (bf16, k perm32, colsums from bf16 values)
    prep_kernel<<<N_QKV + CC, 128>>>(w_qkv, b_qkv, ln_gamma, ln_beta, w_proj);

    // 3. QKV GEMM (bf16; LN fused; Q fp32, K/V bf16 attention layouts)
    qkv_gemm<<<dim3(BLT / 128, N_QKV / 128), 256, GSMEM>>>();

    // 4. Attention (R15 config; output bf16 perm32 -> g_ob)
    attn_mma<<<dim3(LL / 64, HH, BB), 128, AT_SMEM_BYTES>>>();

    // 5. Proj GEMM (bf16) + bias + residual
    proj_gemm<<<dim3(BLT / 128, CC / 128), 256, GSMEM>>>(b_proj, x, out);
}